// round 10
// baseline (speedup 1.0000x reference)
#include <cuda_runtime.h>
#include <cuda_bf16.h>
#include <cstdint>

// Problem constants (fixed-shape benchmark)
#define H      1024
#define BATCH  32
#define NN     20        // N
#define KKK    10        // K (group size)
#define NK     200       // N*K
#define QQ     2048      // Q_total
#define SROWS  (BATCH * NK)   // 6400 support rows
#define QROWS  (BATCH * QQ)   // 65536 query rows

// Scratch (allocation-free: __device__ globals) — support LN only
__device__ __nv_bfloat16 g_sh[(size_t)SROWS * H];   // support LN hi
__device__ __nv_bfloat16 g_sl[(size_t)SROWS * H];   // support LN lo

// ---------------------------------------------------------------------------
// LayerNorm for SUPPORT rows, warp-per-row: 8 warps/block = 8 rows/block.
// ---------------------------------------------------------------------------
__global__ __launch_bounds__(256) void ln_kernel(const float* __restrict__ x,
                          const float* __restrict__ gamma,
                          const float* __restrict__ beta) {
    const int lane = threadIdx.x & 31;
    const int warp = threadIdx.x >> 5;
    const int row  = blockIdx.x * 8 + warp;

    const float4* xr = reinterpret_cast<const float4*>(x) + (size_t)row * (H / 4);
    float4 a[8];
    #pragma unroll
    for (int i = 0; i < 8; i++) a[i] = xr[lane + i * 32];

    float s = 0.0f, ss = 0.0f;
    #pragma unroll
    for (int i = 0; i < 8; i++) {
        s  += (a[i].x + a[i].y) + (a[i].z + a[i].w);
        ss += fmaf(a[i].x, a[i].x, fmaf(a[i].y, a[i].y,
               fmaf(a[i].z, a[i].z, a[i].w * a[i].w)));
    }
    #pragma unroll
    for (int o = 16; o; o >>= 1) {
        s  += __shfl_xor_sync(0xffffffffu, s, o);
        ss += __shfl_xor_sync(0xffffffffu, ss, o);
    }
    const float mean = s * (1.0f / H);
    const float var  = ss * (1.0f / H) - mean * mean;
    const float rstd = rsqrtf(var + 1e-5f);

    uint2* dsth = reinterpret_cast<uint2*>(g_sh + (size_t)row * H);
    uint2* dstl = reinterpret_cast<uint2*>(g_sl + (size_t)row * H);
    const float4* g4 = reinterpret_cast<const float4*>(gamma);
    const float4* b4 = reinterpret_cast<const float4*>(beta);

    #pragma unroll
    for (int i = 0; i < 8; i++) {
        const int idx = lane + i * 32;
        float4 g  = g4[idx];
        float4 bb = b4[idx];
        float o0 = (a[i].x - mean) * rstd * g.x + bb.x;
        float o1 = (a[i].y - mean) * rstd * g.y + bb.y;
        float o2 = (a[i].z - mean) * rstd * g.z + bb.z;
        float o3 = (a[i].w - mean) * rstd * g.w + bb.w;

        __nv_bfloat162 h01 = __floats2bfloat162_rn(o0, o1);
        __nv_bfloat162 h23 = __floats2bfloat162_rn(o2, o3);
        uint2 hp;
        hp.x = *reinterpret_cast<unsigned*>(&h01);
        hp.y = *reinterpret_cast<unsigned*>(&h23);
        dsth[idx] = hp;

        __nv_bfloat162 l01 = __floats2bfloat162_rn(o0 - __bfloat162float(h01.x),
                                                   o1 - __bfloat162float(h01.y));
        __nv_bfloat162 l23 = __floats2bfloat162_rn(o2 - __bfloat162float(h23.x),
                                                   o3 - __bfloat162float(h23.y));
        uint2 lp;
        lp.x = *reinterpret_cast<unsigned*>(&l01);
        lp.y = *reinterpret_cast<unsigned*>(&l23);
        dstl[idx] = lp;
    }
}

// ---------------------------------------------------------------------------
// Fused kernel: query LN (stats prologue + on-the-fly split-bf16 convert)
// + tensor-core batched GEMM (split-bf16 x3) + max/min/argmax epilogue.
// CTA tile: BM=128 x BN=208, BK=32. 512 threads / 16 warps, warp tile 16x104.
// ldmatrix fragment loads; MMA stream reordered so same-accumulator RAW
// distance is 6-7 (was 2) to cover HMMA latency.
// ---------------------------------------------------------------------------
#define BM   128
#define BN   208
#define BKG  32
#define BKP  40          // padded smem k-stride (bf16); conflict-free LDSM
#define NTHR 512

#define AH_B      (BM * BKP * 2)            // 10240
#define ABUF_B    (2 * AH_B)                // 20480 (Ah + Al)
#define OFF_BRING (2 * ABUF_B)              // 40960
#define BH_B      (BN * BKP * 2)            // 16640
#define BSTG_B    (2 * BH_B)                // 33280 (Bh + Bl)
#define OFF_GM    (OFF_BRING + 3 * BSTG_B)  // 140800
#define OFF_BT    (OFF_GM + 4096)           // 144896
#define OFF_ST    (OFF_BT + 4096)           // 148992 (mean[128], rstd[128])
#define SMEM_TOTAL (OFF_ST + 1024)          // 150016
#define ZST       210                       // epilogue smem row stride (floats)

__device__ __forceinline__ void cp16(uint32_t dst, const void* src, bool full) {
    int sz = full ? 16 : 0;
    asm volatile("cp.async.cg.shared.global [%0], [%1], 16, %2;\n"
                 :: "r"(dst), "l"(src), "r"(sz));
}

__device__ __forceinline__ void mma_bf16(float c[4],
                                         const unsigned a[4],
                                         unsigned b0, unsigned b1) {
    asm volatile(
        "mma.sync.aligned.m16n8k16.row.col.f32.bf16.bf16.f32 "
        "{%0,%1,%2,%3}, {%4,%5,%6,%7}, {%8,%9}, {%0,%1,%2,%3};\n"
        : "+f"(c[0]), "+f"(c[1]), "+f"(c[2]), "+f"(c[3])
        : "r"(a[0]), "r"(a[1]), "r"(a[2]), "r"(a[3]), "r"(b0), "r"(b1));
}

__device__ __forceinline__ void ldsm_x4(unsigned r[4], uint32_t addr) {
    asm volatile("ldmatrix.sync.aligned.m8n8.x4.shared.b16 {%0,%1,%2,%3}, [%4];"
                 : "=r"(r[0]), "=r"(r[1]), "=r"(r[2]), "=r"(r[3]) : "r"(addr));
}
__device__ __forceinline__ void ldsm_x2(unsigned r[2], uint32_t addr) {
    asm volatile("ldmatrix.sync.aligned.m8n8.x2.shared.b16 {%0,%1}, [%2];"
                 : "=r"(r[0]), "=r"(r[1]) : "r"(addr));
}

extern __shared__ char dsm[];

__global__ __launch_bounds__(NTHR, 1) void gemm_kernel(const float* __restrict__ query,
                                                       const float* __restrict__ gamma,
                                                       const float* __restrict__ beta,
                                                       float* __restrict__ out_logits,
                                                       float* __restrict__ out_pred,
                                                       int write_pred) {
    const int b    = blockIdx.z;
    const int tm   = blockIdx.y;
    const int tid  = threadIdx.x;
    const int warp = tid >> 5, lane = tid & 31;
    const int wm = warp >> 1, wn = warp & 1;   // 8 m-warps x 2 n-warps
    const int qr = lane >> 2;          // 0..7
    const int qp = (lane & 3) * 2;     // 0,2,4,6

    const float* gq = query + ((size_t)b * QQ + (size_t)tm * BM) * H;
    const __nv_bfloat16* gBh = g_sh + (size_t)b * NK * H;
    const __nv_bfloat16* gBl = g_sl + (size_t)b * NK * H;

    const uint32_t smem_u32 = (uint32_t)__cvta_generic_to_shared(dsm);

    // ---- prologue: gamma/beta -> smem; per-row LN stats -> smem ----
    {
        if (tid < 256) {
            reinterpret_cast<float4*>(dsm + OFF_GM)[tid] =
                reinterpret_cast<const float4*>(gamma)[tid];
            reinterpret_cast<float4*>(dsm + OFF_BT)[tid] =
                reinterpret_cast<const float4*>(beta)[tid];
        }
        float* smean = (float*)(dsm + OFF_ST);
        float* srstd = (float*)(dsm + OFF_ST + 512);
        #pragma unroll 1
        for (int rr = 0; rr < 8; rr++) {
            const int row = warp * 8 + rr;
            const float4* xr = reinterpret_cast<const float4*>(gq + (size_t)row * H);
            float s = 0.0f, ss = 0.0f;
            #pragma unroll
            for (int j = 0; j < 8; j++) {
                float4 a = xr[j * 32 + lane];
                s  += (a.x + a.y) + (a.z + a.w);
                ss += fmaf(a.x, a.x, fmaf(a.y, a.y, fmaf(a.z, a.z, a.w * a.w)));
            }
            #pragma unroll
            for (int o = 16; o; o >>= 1) {
                s  += __shfl_xor_sync(0xffffffffu, s, o);
                ss += __shfl_xor_sync(0xffffffffu, ss, o);
            }
            if (lane == 0) {
                float mean = s * (1.0f / H);
                float var  = ss * (1.0f / H) - mean * mean;
                smean[row] = mean;
                srstd[row] = rsqrtf(var + 1e-5f);
            }
        }
    }
    __syncthreads();

    // per-thread A assignment: row = tid>>2, k-eighth = (tid&3)*8
    const int arow = tid >> 2;
    const int ak0  = (tid & 3) * 8;
    const float amean = ((const float*)(dsm + OFF_ST))[arow];
    const float arstd = ((const float*)(dsm + OFF_ST + 512))[arow];
    const float* arow_p = gq + (size_t)arow * H;

    // ldmatrix lane->tile-row/col mappings
    const int a_lrow = wm * 16 + (lane & 7) + ((lane >> 3) & 1) * 8;
    const int a_lcol = ((lane >> 4) & 1) * 8;
    const int b_lrow = wn * 104 + (lane & 7) + ((lane >> 4) & 1) * 8;
    const int b_lcol = ((lane >> 3) & 1) * 8;
    const int t_lrow = wn * 104 + 96 + (lane & 7);
    const int t_lcol = ((lane >> 3) & 1) * 8;

    float acc[13][4];
    #pragma unroll
    for (int nf = 0; nf < 13; nf++)
        #pragma unroll
        for (int i = 0; i < 4; i++) acc[nf][i] = 0.0f;

    // ---- B stage loader (cp.async) ----
    auto issueB = [&](int s, int buf) {
        const int kt = s * BKG;
        uint32_t base = smem_u32 + OFF_BRING + buf * BSTG_B;
        #pragma unroll
        for (int it = 0; it < 2; it++) {
            int idx = tid + it * NTHR;           // need < 832
            if (idx < 832) {
                int r = idx >> 2, k0 = (idx & 3) * 8;
                uint32_t off = (uint32_t)(r * BKP + k0) * 2;
                bool v = (r < NK);
                int rs = v ? r : 0;
                cp16(base + off,        gBh + (size_t)rs * H + kt + k0, v);
                cp16(base + BH_B + off, gBl + (size_t)rs * H + kt + k0, v);
            }
        }
        asm volatile("cp.async.commit_group;\n" ::);
    };

    // ---- A fetch (LDG fp32) + convert (LN affine -> split bf16 -> STS) ----
    float4 av[2];
    auto fetchA = [&](int s) {
        const float4* src = reinterpret_cast<const float4*>(arow_p + s * BKG + ak0);
        av[0] = src[0];
        av[1] = src[1];
    };
    auto convertA = [&](int s) {
        char* ab = dsm + (s & 1) * ABUF_B;
        uint2* dh = reinterpret_cast<uint2*>(ab + (arow * BKP + ak0) * 2);
        uint2* dl = reinterpret_cast<uint2*>(ab + AH_B + (arow * BKP + ak0) * 2);
        const float4* gg = reinterpret_cast<const float4*>(dsm + OFF_GM) + ((s * BKG + ak0) >> 2);
        const float4* bt = reinterpret_cast<const float4*>(dsm + OFF_BT) + ((s * BKG + ak0) >> 2);
        #pragma unroll
        for (int j = 0; j < 2; j++) {
            float4 x = av[j];
            float4 g = gg[j];
            float4 bb = bt[j];
            float o0 = (x.x - amean) * arstd * g.x + bb.x;
            float o1 = (x.y - amean) * arstd * g.y + bb.y;
            float o2 = (x.z - amean) * arstd * g.z + bb.z;
            float o3 = (x.w - amean) * arstd * g.w + bb.w;
            __nv_bfloat162 h01 = __floats2bfloat162_rn(o0, o1);
            __nv_bfloat162 h23 = __floats2bfloat162_rn(o2, o3);
            uint2 hp;
            hp.x = *reinterpret_cast<unsigned*>(&h01);
            hp.y = *reinterpret_cast<unsigned*>(&h23);
            dh[j] = hp;
            __nv_bfloat162 l01 = __floats2bfloat162_rn(o0 - __bfloat162float(h01.x),
                                                       o1 - __bfloat162float(h01.y));
            __nv_bfloat162 l23 = __floats2bfloat162_rn(o2 - __bfloat162float(h23.x),
                                                       o3 - __bfloat162float(h23.y));
            uint2 lp;
            lp.x = *reinterpret_cast<unsigned*>(&l01);
            lp.y = *reinterpret_cast<unsigned*>(&l23);
            dl[j] = lp;
        }
    };

    fetchA(0);
    issueB(0, 0);
    issueB(1, 1);
    convertA(0);
    fetchA(1);

    const int NIT = H / BKG;   // 32
    for (int i = 0; i < NIT; i++) {
        if (i < NIT - 1) asm volatile("cp.async.wait_group 1;\n" ::);
        else             asm volatile("cp.async.wait_group 0;\n" ::);
        __syncthreads();                      // A buf (i&1) + B stage i visible
        if (i + 2 < NIT) issueB(i + 2, (i + 2) % 3);

        const uint32_t abase = smem_u32 + (i & 1) * ABUF_B;
        const uint32_t bbase = smem_u32 + OFF_BRING + (i % 3) * BSTG_B;

        #pragma unroll
        for (int ks = 0; ks < BKG; ks += 16) {
            unsigned ah[4], al[4];
            {
                uint32_t aaddr = abase + (uint32_t)(a_lrow * BKP + ks + a_lcol) * 2;
                ldsm_x4(ah, aaddr);
                ldsm_x4(al, aaddr + AH_B);
            }

            // ---- group A: n-fragments 0..5 (p = 0..2) ----
            unsigned bh[3][4], bl[3][4];
            #pragma unroll
            for (int p = 0; p < 3; p++) {
                uint32_t baddr = bbase +
                    (uint32_t)((b_lrow + p * 16) * BKP + ks + b_lcol) * 2;
                ldsm_x4(bh[p], baddr);
                ldsm_x4(bl[p], baddr + BH_B);
            }
            #pragma unroll
            for (int p = 0; p < 3; p++) {          // pass 1: ah . bh
                mma_bf16(acc[2 * p],     ah, bh[p][0], bh[p][1]);
                mma_bf16(acc[2 * p + 1], ah, bh[p][2], bh[p][3]);
            }
            #pragma unroll
            for (int p = 0; p < 3; p++) {          // pass 2: ah . bl
                mma_bf16(acc[2 * p],     ah, bl[p][0], bl[p][1]);
                mma_bf16(acc[2 * p + 1], ah, bl[p][2], bl[p][3]);
            }
            #pragma unroll
            for (int p = 0; p < 3; p++) {          // pass 3: al . bh
                mma_bf16(acc[2 * p],     al, bh[p][0], bh[p][1]);
                mma_bf16(acc[2 * p + 1], al, bh[p][2], bh[p][3]);
            }

            // ---- group B: n-fragments 6..12 (p = 3..5 + x2 tail) ----
            unsigned th[2], tl[2];
            #pragma unroll
            for (int p = 0; p < 3; p++) {
                uint32_t baddr = bbase +
                    (uint32_t)((b_lrow + (p + 3) * 16) * BKP + ks + b_lcol) * 2;
                ldsm_x4(bh[p], baddr);
                ldsm_x4(bl[p], baddr + BH_B);
            }
            {
                uint32_t taddr = bbase +
                    (uint32_t)(t_lrow * BKP + ks + t_lcol) * 2;
                ldsm_x2(th, taddr);
                ldsm_x2(tl, taddr + BH_B);
            }
            #pragma unroll
            for (int p = 0; p < 3; p++) {          // pass 1: ah . bh
                mma_bf16(acc[6 + 2 * p], ah, bh[p][0], bh[p][1]);
                mma_bf16(acc[7 + 2 * p], ah, bh[p][2], bh[p][3]);
            }
            mma_bf16(acc[12], ah, th[0], th[1]);
            #pragma unroll
            for (int p = 0; p < 3; p++) {          // pass 2: ah . bl
                mma_bf16(acc[6 + 2 * p], ah, bl[p][0], bl[p][1]);
                mma_bf16(acc[7 + 2 * p], ah, bl[p][2], bl[p][3]);
            }
            mma_bf16(acc[12], ah, tl[0], tl[1]);
            #pragma unroll
            for (int p = 0; p < 3; p++) {          // pass 3: al . bh
                mma_bf16(acc[6 + 2 * p], al, bh[p][0], bh[p][1]);
                mma_bf16(acc[7 + 2 * p], al, bh[p][2], bh[p][3]);
            }
            mma_bf16(acc[12], al, th[0], th[1]);
        }

        // prepare next A stage (writes buf (i+1)&1, not read until next sync)
        if (i + 1 < NIT) {
            convertA(i + 1);
            if (i + 2 < NIT) fetchA(i + 2);
        }
    }

    // ---- fused epilogue: all 128 rows staged at once ----
    __syncthreads();
    float* zs = (float*)dsm;                    // 128 x ZST floats = 107.5 KB
    #pragma unroll
    for (int nf = 0; nf < 13; nf++) {
        int r0  = wm * 16 + qr;
        int col = wn * 104 + nf * 8 + qp;
        *reinterpret_cast<float2*>(&zs[r0 * ZST + col]) =
            make_float2(acc[nf][0], acc[nf][1]);
        *reinterpret_cast<float2*>(&zs[(r0 + 8) * ZST + col]) =
            make_float2(acc[nf][2], acc[nf][3]);
    }
    __syncthreads();

    const float NEGF = -3.402823466e38f;
    const float POSF =  3.402823466e38f;
    #pragma unroll 1
    for (int rr = 0; rr < 8; rr++) {
        int rl = warp * 8 + rr;
        int gq_ = tm * BM + rl;
        size_t orow = ((size_t)b * QQ + gq_) * (NN + 1);

        float m = NEGF;
        if (lane < NN) {
            #pragma unroll
            for (int j = 0; j < KKK; j++)
                m = fmaxf(m, zs[rl * ZST + lane * KKK + j]);
            out_logits[orow + lane] = m;
        }

        float mv = (lane < NN) ? m : POSF;
        #pragma unroll
        for (int o = 16; o; o >>= 1)
            mv = fminf(mv, __shfl_xor_sync(0xffffffffu, mv, o));
        if (lane == 0) out_logits[orow + NN] = mv - 1.0f;

        float v  = (lane < NN) ? m : NEGF;
        int  idx = lane;
        #pragma unroll
        for (int o = 16; o; o >>= 1) {
            float ov = __shfl_xor_sync(0xffffffffu, v, o);
            int   oi = __shfl_xor_sync(0xffffffffu, idx, o);
            if (ov > v || (ov == v && oi < idx)) { v = ov; idx = oi; }
        }
        if (lane == 0 && write_pred)
            out_pred[(size_t)b * QQ + gq_] = (float)idx;
    }
}

// ---------------------------------------------------------------------------
extern "C" void kernel_launch(void* const* d_in, const int* in_sizes, int n_in,
                              void* d_out, int out_size) {
    const float* support = (const float*)d_in[0];
    const float* query   = (const float*)d_in[1];
    const float* gamma   = (const float*)d_in[2];
    const float* beta    = (const float*)d_in[3];
    float* out = (float*)d_out;

    cudaFuncSetAttribute(gemm_kernel,
                         cudaFuncAttributeMaxDynamicSharedMemorySize, SMEM_TOTAL);

    ln_kernel<<<SROWS / 8, 256>>>(support, gamma, beta);

    const int logits_elems = BATCH * QQ * (NN + 1);  // 1,376,256
    const int write_pred   = (out_size >= logits_elems + QROWS) ? 1 : 0;

    dim3 grid(1, QQ / BM, BATCH);   // (1, 16, 32) = 512 CTAs
    gemm_kernel<<<grid, NTHR, SMEM_TOTAL>>>(query, gamma, beta,
                                            out, out + logits_elems, write_pred);
}

// round 11
// speedup vs baseline: 1.0231x; 1.0231x over previous
#include <cuda_runtime.h>
#include <cuda_bf16.h>
#include <cstdint>

// Problem constants (fixed-shape benchmark)
#define H      1024
#define BATCH  32
#define NN     20        // N
#define KKK    10        // K (group size)
#define NK     200       // N*K
#define QQ     2048      // Q_total
#define SROWS  (BATCH * NK)   // 6400 support rows
#define QROWS  (BATCH * QQ)   // 65536 query rows

// Scratch (allocation-free: __device__ globals) — support LN only
__device__ __nv_bfloat16 g_sh[(size_t)SROWS * H];   // support LN hi
__device__ __nv_bfloat16 g_sl[(size_t)SROWS * H];   // support LN lo

// ---------------------------------------------------------------------------
// LayerNorm for SUPPORT rows, warp-per-row: 8 warps/block = 8 rows/block.
// ---------------------------------------------------------------------------
__global__ __launch_bounds__(256) void ln_kernel(const float* __restrict__ x,
                          const float* __restrict__ gamma,
                          const float* __restrict__ beta) {
    const int lane = threadIdx.x & 31;
    const int warp = threadIdx.x >> 5;
    const int row  = blockIdx.x * 8 + warp;

    const float4* xr = reinterpret_cast<const float4*>(x) + (size_t)row * (H / 4);
    float4 a[8];
    #pragma unroll
    for (int i = 0; i < 8; i++) a[i] = xr[lane + i * 32];

    float s = 0.0f, ss = 0.0f;
    #pragma unroll
    for (int i = 0; i < 8; i++) {
        s  += (a[i].x + a[i].y) + (a[i].z + a[i].w);
        ss += fmaf(a[i].x, a[i].x, fmaf(a[i].y, a[i].y,
               fmaf(a[i].z, a[i].z, a[i].w * a[i].w)));
    }
    #pragma unroll
    for (int o = 16; o; o >>= 1) {
        s  += __shfl_xor_sync(0xffffffffu, s, o);
        ss += __shfl_xor_sync(0xffffffffu, ss, o);
    }
    const float mean = s * (1.0f / H);
    const float var  = ss * (1.0f / H) - mean * mean;
    const float rstd = rsqrtf(var + 1e-5f);

    uint2* dsth = reinterpret_cast<uint2*>(g_sh + (size_t)row * H);
    uint2* dstl = reinterpret_cast<uint2*>(g_sl + (size_t)row * H);
    const float4* g4 = reinterpret_cast<const float4*>(gamma);
    const float4* b4 = reinterpret_cast<const float4*>(beta);

    #pragma unroll
    for (int i = 0; i < 8; i++) {
        const int idx = lane + i * 32;
        float4 g  = g4[idx];
        float4 bb = b4[idx];
        float o0 = (a[i].x - mean) * rstd * g.x + bb.x;
        float o1 = (a[i].y - mean) * rstd * g.y + bb.y;
        float o2 = (a[i].z - mean) * rstd * g.z + bb.z;
        float o3 = (a[i].w - mean) * rstd * g.w + bb.w;

        __nv_bfloat162 h01 = __floats2bfloat162_rn(o0, o1);
        __nv_bfloat162 h23 = __floats2bfloat162_rn(o2, o3);
        uint2 hp;
        hp.x = *reinterpret_cast<unsigned*>(&h01);
        hp.y = *reinterpret_cast<unsigned*>(&h23);
        dsth[idx] = hp;

        __nv_bfloat162 l01 = __floats2bfloat162_rn(o0 - __bfloat162float(h01.x),
                                                   o1 - __bfloat162float(h01.y));
        __nv_bfloat162 l23 = __floats2bfloat162_rn(o2 - __bfloat162float(h23.x),
                                                   o3 - __bfloat162float(h23.y));
        uint2 lp;
        lp.x = *reinterpret_cast<unsigned*>(&l01);
        lp.y = *reinterpret_cast<unsigned*>(&l23);
        dstl[idx] = lp;
    }
}

// ---------------------------------------------------------------------------
// Fused kernel: query LN (stats prologue + on-the-fly split-bf16 convert)
// + tensor-core batched GEMM (split-bf16 x3) + max/min/argmax epilogue.
// CTA tile: BM=128 x BN=224 (valid 208; rows 200+ zero-filled), BK=32.
// 512 threads / 16 warps in a 4x4 grid; warp tile 32x56.
// Fragment redundancy: A 4x, B 4x (was 2x/8x) -> smem reads ~88KB/kstep.
// ---------------------------------------------------------------------------
#define BM   128
#define BN   224         // padded; valid n < BNV
#define BNV  208
#define BKG  32
#define BKP  40          // padded smem k-stride (bf16); conflict-free LDSM
#define NTHR 512

#define AH_B      (BM * BKP * 2)            // 10240
#define ABUF_B    (2 * AH_B)                // 20480 (Ah + Al)
#define OFF_BRING (2 * ABUF_B)              // 40960
#define BH_B      (BN * BKP * 2)            // 17920
#define BSTG_B    (2 * BH_B)                // 35840 (Bh + Bl)
#define OFF_GM    (OFF_BRING + 3 * BSTG_B)  // 148480
#define OFF_BT    (OFF_GM + 4096)           // 152576
#define OFF_ST    (OFF_BT + 4096)           // 156672 (mean[128], rstd[128])
#define SMEM_TOTAL (OFF_ST + 1024)          // 157696
#define ZST       210                       // epilogue smem row stride (floats)

__device__ __forceinline__ void cp16(uint32_t dst, const void* src, bool full) {
    int sz = full ? 16 : 0;
    asm volatile("cp.async.cg.shared.global [%0], [%1], 16, %2;\n"
                 :: "r"(dst), "l"(src), "r"(sz));
}

__device__ __forceinline__ void mma_bf16(float c[4],
                                         const unsigned a[4],
                                         unsigned b0, unsigned b1) {
    asm volatile(
        "mma.sync.aligned.m16n8k16.row.col.f32.bf16.bf16.f32 "
        "{%0,%1,%2,%3}, {%4,%5,%6,%7}, {%8,%9}, {%0,%1,%2,%3};\n"
        : "+f"(c[0]), "+f"(c[1]), "+f"(c[2]), "+f"(c[3])
        : "r"(a[0]), "r"(a[1]), "r"(a[2]), "r"(a[3]), "r"(b0), "r"(b1));
}

__device__ __forceinline__ void ldsm_x4(unsigned r[4], uint32_t addr) {
    asm volatile("ldmatrix.sync.aligned.m8n8.x4.shared.b16 {%0,%1,%2,%3}, [%4];"
                 : "=r"(r[0]), "=r"(r[1]), "=r"(r[2]), "=r"(r[3]) : "r"(addr));
}
__device__ __forceinline__ void ldsm_x2(unsigned r[2], uint32_t addr) {
    asm volatile("ldmatrix.sync.aligned.m8n8.x2.shared.b16 {%0,%1}, [%2];"
                 : "=r"(r[0]), "=r"(r[1]) : "r"(addr));
}

extern __shared__ char dsm[];

__global__ __launch_bounds__(NTHR, 1) void gemm_kernel(const float* __restrict__ query,
                                                       const float* __restrict__ gamma,
                                                       const float* __restrict__ beta,
                                                       float* __restrict__ out_logits,
                                                       float* __restrict__ out_pred,
                                                       int write_pred) {
    const int b    = blockIdx.z;
    const int tm   = blockIdx.y;
    const int tid  = threadIdx.x;
    const int warp = tid >> 5, lane = tid & 31;
    const int wm = warp >> 2, wn = warp & 3;   // 4 m-warps x 4 n-warps
    const int qr = lane >> 2;          // 0..7
    const int qp = (lane & 3) * 2;     // 0,2,4,6

    const float* gq = query + ((size_t)b * QQ + (size_t)tm * BM) * H;
    const __nv_bfloat16* gBh = g_sh + (size_t)b * NK * H;
    const __nv_bfloat16* gBl = g_sl + (size_t)b * NK * H;

    const uint32_t smem_u32 = (uint32_t)__cvta_generic_to_shared(dsm);

    // ---- prologue: gamma/beta -> smem; per-row LN stats -> smem ----
    {
        if (tid < 256) {
            reinterpret_cast<float4*>(dsm + OFF_GM)[tid] =
                reinterpret_cast<const float4*>(gamma)[tid];
            reinterpret_cast<float4*>(dsm + OFF_BT)[tid] =
                reinterpret_cast<const float4*>(beta)[tid];
        }
        float* smean = (float*)(dsm + OFF_ST);
        float* srstd = (float*)(dsm + OFF_ST + 512);
        #pragma unroll 1
        for (int rr = 0; rr < 8; rr++) {
            const int row = warp * 8 + rr;
            const float4* xr = reinterpret_cast<const float4*>(gq + (size_t)row * H);
            float s = 0.0f, ss = 0.0f;
            #pragma unroll
            for (int j = 0; j < 8; j++) {
                float4 a = xr[j * 32 + lane];
                s  += (a.x + a.y) + (a.z + a.w);
                ss += fmaf(a.x, a.x, fmaf(a.y, a.y, fmaf(a.z, a.z, a.w * a.w)));
            }
            #pragma unroll
            for (int o = 16; o; o >>= 1) {
                s  += __shfl_xor_sync(0xffffffffu, s, o);
                ss += __shfl_xor_sync(0xffffffffu, ss, o);
            }
            if (lane == 0) {
                float mean = s * (1.0f / H);
                float var  = ss * (1.0f / H) - mean * mean;
                smean[row] = mean;
                srstd[row] = rsqrtf(var + 1e-5f);
            }
        }
    }
    __syncthreads();

    // per-thread A assignment: row = tid>>2, k-eighth = (tid&3)*8
    const int arow = tid >> 2;
    const int ak0  = (tid & 3) * 8;
    const float amean = ((const float*)(dsm + OFF_ST))[arow];
    const float arstd = ((const float*)(dsm + OFF_ST + 512))[arow];
    const float* arow_p = gq + (size_t)arow * H;

    // ldmatrix lane->tile-row/col mappings
    // A x4 tiles: (m0,k0),(m8,k0),(m0,k8),(m8,k8)
    const int a_lrow0 = wm * 32 + (lane & 7) + ((lane >> 3) & 1) * 8;
    const int a_lcol  = ((lane >> 4) & 1) * 8;
    // B x4 tiles: (n0,k0),(n0,k8),(n8,k0),(n8,k8) -> 2 n-frags
    const int b_lrow0 = wn * 56 + (lane & 7) + ((lane >> 4) & 1) * 8;
    const int b_lcol  = ((lane >> 3) & 1) * 8;
    // B x2 tail (lanes 0-15): (n48,k0),(n48,k8)
    const int t_lrow  = wn * 56 + 48 + (lane & 7);
    const int t_lcol  = ((lane >> 3) & 1) * 8;

    float acc[2][7][4];
    #pragma unroll
    for (int mf = 0; mf < 2; mf++)
        #pragma unroll
        for (int nf = 0; nf < 7; nf++)
            #pragma unroll
            for (int i = 0; i < 4; i++) acc[mf][nf][i] = 0.0f;

    // ---- B stage loader (cp.async; rows >= NK zero-filled) ----
    auto issueB = [&](int s, int buf) {
        const int kt = s * BKG;
        uint32_t base = smem_u32 + OFF_BRING + buf * BSTG_B;
        #pragma unroll
        for (int it = 0; it < 2; it++) {
            int idx = tid + it * NTHR;           // need < 896 (224 rows x 4)
            if (idx < 896) {
                int r = idx >> 2, k0 = (idx & 3) * 8;
                uint32_t off = (uint32_t)(r * BKP + k0) * 2;
                bool v = (r < NK);
                int rs = v ? r : 0;
                cp16(base + off,        gBh + (size_t)rs * H + kt + k0, v);
                cp16(base + BH_B + off, gBl + (size_t)rs * H + kt + k0, v);
            }
        }
        asm volatile("cp.async.commit_group;\n" ::);
    };

    // ---- A fetch (LDG fp32) + convert (LN affine -> split bf16 -> STS) ----
    float4 av[2];
    auto fetchA = [&](int s) {
        const float4* src = reinterpret_cast<const float4*>(arow_p + s * BKG + ak0);
        av[0] = src[0];
        av[1] = src[1];
    };
    auto convertA = [&](int s) {
        char* ab = dsm + (s & 1) * ABUF_B;
        uint2* dh = reinterpret_cast<uint2*>(ab + (arow * BKP + ak0) * 2);
        uint2* dl = reinterpret_cast<uint2*>(ab + AH_B + (arow * BKP + ak0) * 2);
        const float4* gg = reinterpret_cast<const float4*>(dsm + OFF_GM) + ((s * BKG + ak0) >> 2);
        const float4* bt = reinterpret_cast<const float4*>(dsm + OFF_BT) + ((s * BKG + ak0) >> 2);
        #pragma unroll
        for (int j = 0; j < 2; j++) {
            float4 x = av[j];
            float4 g = gg[j];
            float4 bb = bt[j];
            float o0 = (x.x - amean) * arstd * g.x + bb.x;
            float o1 = (x.y - amean) * arstd * g.y + bb.y;
            float o2 = (x.z - amean) * arstd * g.z + bb.z;
            float o3 = (x.w - amean) * arstd * g.w + bb.w;
            __nv_bfloat162 h01 = __floats2bfloat162_rn(o0, o1);
            __nv_bfloat162 h23 = __floats2bfloat162_rn(o2, o3);
            uint2 hp;
            hp.x = *reinterpret_cast<unsigned*>(&h01);
            hp.y = *reinterpret_cast<unsigned*>(&h23);
            dh[j] = hp;
            __nv_bfloat162 l01 = __floats2bfloat162_rn(o0 - __bfloat162float(h01.x),
                                                       o1 - __bfloat162float(h01.y));
            __nv_bfloat162 l23 = __floats2bfloat162_rn(o2 - __bfloat162float(h23.x),
                                                       o3 - __bfloat162float(h23.y));
            uint2 lp;
            lp.x = *reinterpret_cast<unsigned*>(&l01);
            lp.y = *reinterpret_cast<unsigned*>(&l23);
            dl[j] = lp;
        }
    };

    fetchA(0);
    issueB(0, 0);
    issueB(1, 1);
    convertA(0);
    fetchA(1);

    const int NIT = H / BKG;   // 32
    for (int i = 0; i < NIT; i++) {
        if (i < NIT - 1) asm volatile("cp.async.wait_group 1;\n" ::);
        else             asm volatile("cp.async.wait_group 0;\n" ::);
        __syncthreads();                      // A buf (i&1) + B stage i visible
        if (i + 2 < NIT) issueB(i + 2, (i + 2) % 3);

        const uint32_t abase = smem_u32 + (i & 1) * ABUF_B;
        const uint32_t bbase = smem_u32 + OFF_BRING + (i % 3) * BSTG_B;

        #pragma unroll
        for (int ks = 0; ks < BKG; ks += 16) {
            unsigned ah[2][4], al[2][4];
            #pragma unroll
            for (int mf = 0; mf < 2; mf++) {
                uint32_t aaddr = abase +
                    (uint32_t)((a_lrow0 + mf * 16) * BKP + ks + a_lcol) * 2;
                ldsm_x4(ah[mf], aaddr);
                ldsm_x4(al[mf], aaddr + AH_B);
            }
            #pragma unroll
            for (int p = 0; p < 3; p++) {
                unsigned bh[4], bl[4];
                uint32_t baddr = bbase +
                    (uint32_t)((b_lrow0 + p * 16) * BKP + ks + b_lcol) * 2;
                ldsm_x4(bh, baddr);
                ldsm_x4(bl, baddr + BH_B);
                // pass 1: ah . bh
                mma_bf16(acc[0][2 * p],     ah[0], bh[0], bh[1]);
                mma_bf16(acc[1][2 * p],     ah[1], bh[0], bh[1]);
                mma_bf16(acc[0][2 * p + 1], ah[0], bh[2], bh[3]);
                mma_bf16(acc[1][2 * p + 1], ah[1], bh[2], bh[3]);
                // pass 2: ah . bl
                mma_bf16(acc[0][2 * p],     ah[0], bl[0], bl[1]);
                mma_bf16(acc[1][2 * p],     ah[1], bl[0], bl[1]);
                mma_bf16(acc[0][2 * p + 1], ah[0], bl[2], bl[3]);
                mma_bf16(acc[1][2 * p + 1], ah[1], bl[2], bl[3]);
                // pass 3: al . bh
                mma_bf16(acc[0][2 * p],     al[0], bh[0], bh[1]);
                mma_bf16(acc[1][2 * p],     al[1], bh[0], bh[1]);
                mma_bf16(acc[0][2 * p + 1], al[0], bh[2], bh[3]);
                mma_bf16(acc[1][2 * p + 1], al[1], bh[2], bh[3]);
            }
            {   // tail nf = 6 (n 48..55 of this warp's slice)
                unsigned th[2], tl[2];
                uint32_t taddr = bbase +
                    (uint32_t)(t_lrow * BKP + ks + t_lcol) * 2;
                ldsm_x2(th, taddr);
                ldsm_x2(tl, taddr + BH_B);
                mma_bf16(acc[0][6], ah[0], th[0], th[1]);
                mma_bf16(acc[1][6], ah[1], th[0], th[1]);
                mma_bf16(acc[0][6], ah[0], tl[0], tl[1]);
                mma_bf16(acc[1][6], ah[1], tl[0], tl[1]);
                mma_bf16(acc[0][6], al[0], th[0], th[1]);
                mma_bf16(acc[1][6], al[1], th[0], th[1]);
            }
        }

        // prepare next A stage (writes buf (i+1)&1, not read until next sync)
        if (i + 1 < NIT) {
            convertA(i + 1);
            if (i + 2 < NIT) fetchA(i + 2);
        }
    }

    // ---- fused epilogue: all 128 rows staged at once ----
    __syncthreads();
    float* zs = (float*)dsm;                    // 128 x ZST floats = 107.5 KB
    #pragma unroll
    for (int mf = 0; mf < 2; mf++)
        #pragma unroll
        for (int nf = 0; nf < 7; nf++) {
            int colbase = wn * 56 + nf * 8;
            if (colbase < BNV) {                // skip zero-pad fragments
                int r0  = wm * 32 + mf * 16 + qr;
                int col = colbase + qp;
                *reinterpret_cast<float2*>(&zs[r0 * ZST + col]) =
                    make_float2(acc[mf][nf][0], acc[mf][nf][1]);
                *reinterpret_cast<float2*>(&zs[(r0 + 8) * ZST + col]) =
                    make_float2(acc[mf][nf][2], acc[mf][nf][3]);
            }
        }
    __syncthreads();

    const float NEGF = -3.402823466e38f;
    const float POSF =  3.402823466e38f;
    #pragma unroll 1
    for (int rr = 0; rr < 8; rr++) {
        int rl = warp * 8 + rr;
        int gq_ = tm * BM + rl;
        size_t orow = ((size_t)b * QQ + gq_) * (NN + 1);

        float m = NEGF;
        if (lane < NN) {
            #pragma unroll
            for (int j = 0; j < KKK; j++)
                m = fmaxf(m, zs[rl * ZST + lane * KKK + j]);
            out_logits[orow + lane] = m;
        }

        float mv = (lane < NN) ? m : POSF;
        #pragma unroll
        for (int o = 16; o; o >>= 1)
            mv = fminf(mv, __shfl_xor_sync(0xffffffffu, mv, o));
        if (lane == 0) out_logits[orow + NN] = mv - 1.0f;

        float v  = (lane < NN) ? m : NEGF;
        int  idx = lane;
        #pragma unroll
        for (int o = 16; o; o >>= 1) {
            float ov = __shfl_xor_sync(0xffffffffu, v, o);
            int   oi = __shfl_xor_sync(0xffffffffu, idx, o);
            if (ov > v || (ov == v && oi < idx)) { v = ov; idx = oi; }
        }
        if (lane == 0 && write_pred)
            out_pred[(size_t)b * QQ + gq_] = (float)idx;
    }
}

// ---------------------------------------------------------------------------
extern "C" void kernel_launch(void* const* d_in, const int* in_sizes, int n_in,
                              void* d_out, int out_size) {
    const float* support = (const float*)d_in[0];
    const float* query   = (const float*)d_in[1];
    const float* gamma   = (const float*)d_in[2];
    const float* beta    = (const float*)d_in[3];
    float* out = (float*)d_out;

    cudaFuncSetAttribute(gemm_kernel,
                         cudaFuncAttributeMaxDynamicSharedMemorySize, SMEM_TOTAL);

    ln_kernel<<<SROWS / 8, 256>>>(support, gamma, beta);

    const int logits_elems = BATCH * QQ * (NN + 1);  // 1,376,256
    const int write_pred   = (out_size >= logits_elems + QROWS) ? 1 : 0;

    dim3 grid(1, QQ / BM, BATCH);   // (1, 16, 32) = 512 CTAs
    gemm_kernel<<<grid, NTHR, SMEM_TOTAL>>>(query, gamma, beta,
                                            out, out + logits_elems, write_pred);
}

// round 12
// speedup vs baseline: 1.0908x; 1.0662x over previous
#include <cuda_runtime.h>
#include <cuda_bf16.h>
#include <cstdint>

// Problem constants (fixed-shape benchmark)
#define H      1024
#define BATCH  32
#define NN     20        // N
#define KKK    10        // K (group size)
#define NK     200       // N*K
#define QQ     2048      // Q_total
#define SROWS  (BATCH * NK)   // 6400 support rows
#define QROWS  (BATCH * QQ)   // 65536 query rows

// Scratch (allocation-free: __device__ globals) — support LN only
__device__ __nv_bfloat16 g_sh[(size_t)SROWS * H];   // support LN hi
__device__ __nv_bfloat16 g_sl[(size_t)SROWS * H];   // support LN lo

// ---------------------------------------------------------------------------
// LayerNorm for SUPPORT rows, warp-per-row: 8 warps/block = 8 rows/block.
// ---------------------------------------------------------------------------
__global__ __launch_bounds__(256) void ln_kernel(const float* __restrict__ x,
                          const float* __restrict__ gamma,
                          const float* __restrict__ beta) {
    const int lane = threadIdx.x & 31;
    const int warp = threadIdx.x >> 5;
    const int row  = blockIdx.x * 8 + warp;

    const float4* xr = reinterpret_cast<const float4*>(x) + (size_t)row * (H / 4);
    float4 a[8];
    #pragma unroll
    for (int i = 0; i < 8; i++) a[i] = xr[lane + i * 32];

    float s = 0.0f, ss = 0.0f;
    #pragma unroll
    for (int i = 0; i < 8; i++) {
        s  += (a[i].x + a[i].y) + (a[i].z + a[i].w);
        ss += fmaf(a[i].x, a[i].x, fmaf(a[i].y, a[i].y,
               fmaf(a[i].z, a[i].z, a[i].w * a[i].w)));
    }
    #pragma unroll
    for (int o = 16; o; o >>= 1) {
        s  += __shfl_xor_sync(0xffffffffu, s, o);
        ss += __shfl_xor_sync(0xffffffffu, ss, o);
    }
    const float mean = s * (1.0f / H);
    const float var  = ss * (1.0f / H) - mean * mean;
    const float rstd = rsqrtf(var + 1e-5f);

    uint2* dsth = reinterpret_cast<uint2*>(g_sh + (size_t)row * H);
    uint2* dstl = reinterpret_cast<uint2*>(g_sl + (size_t)row * H);
    const float4* g4 = reinterpret_cast<const float4*>(gamma);
    const float4* b4 = reinterpret_cast<const float4*>(beta);

    #pragma unroll
    for (int i = 0; i < 8; i++) {
        const int idx = lane + i * 32;
        float4 g  = g4[idx];
        float4 bb = b4[idx];
        float o0 = (a[i].x - mean) * rstd * g.x + bb.x;
        float o1 = (a[i].y - mean) * rstd * g.y + bb.y;
        float o2 = (a[i].z - mean) * rstd * g.z + bb.z;
        float o3 = (a[i].w - mean) * rstd * g.w + bb.w;

        __nv_bfloat162 h01 = __floats2bfloat162_rn(o0, o1);
        __nv_bfloat162 h23 = __floats2bfloat162_rn(o2, o3);
        uint2 hp;
        hp.x = *reinterpret_cast<unsigned*>(&h01);
        hp.y = *reinterpret_cast<unsigned*>(&h23);
        dsth[idx] = hp;

        __nv_bfloat162 l01 = __floats2bfloat162_rn(o0 - __bfloat162float(h01.x),
                                                   o1 - __bfloat162float(h01.y));
        __nv_bfloat162 l23 = __floats2bfloat162_rn(o2 - __bfloat162float(h23.x),
                                                   o3 - __bfloat162float(h23.y));
        uint2 lp;
        lp.x = *reinterpret_cast<unsigned*>(&l01);
        lp.y = *reinterpret_cast<unsigned*>(&l23);
        dstl[idx] = lp;
    }
}

// ---------------------------------------------------------------------------
// Fused kernel: query LN (stats prologue + on-the-fly split-bf16 convert)
// + tensor-core batched GEMM (split-bf16 x3) + max/min/argmax epilogue.
// CTA tile: BM=64 x BN=224 (valid outputs n<200), BK=32.
// 256 threads / 8 warps in a 2x4 grid; warp tile 32x56.
// TWO CTAs per SM (launch_bounds(256,2)) — co-resident CTA hides barriers,
// cp.async arrival and LDSM bursts that stalled the 1-CTA/SM version.
// ---------------------------------------------------------------------------
#define BM   64
#define BN   224         // padded; valid output n < NK (200)
#define BNV  208
#define BKG  32
#define BKP  40          // padded smem k-stride (bf16); conflict-free LDSM
#define NTHR 256

#define AH_B      (BM * BKP * 2)            // 5120
#define ABUF_B    (2 * AH_B)                // 10240 (Ah + Al)
#define OFF_BRING (2 * ABUF_B)              // 20480
#define BH_B      (BN * BKP * 2)            // 17920
#define BSTG_B    (2 * BH_B)                // 35840 (Bh + Bl)
#define NBSTG     2
#define OFF_GM    (OFF_BRING + NBSTG * BSTG_B)  // 92160
#define OFF_BT    (OFF_GM + 4096)           // 96256
#define OFF_ST    (OFF_BT + 4096)           // 100352 (mean[64], rstd[64])
#define SMEM_TOTAL (OFF_ST + 1024)          // 101376 (x2 CTAs = 198KB < 228KB)
#define ZST       210                       // epilogue smem row stride (floats)

__device__ __forceinline__ void cp16(uint32_t dst, const void* src, bool full) {
    int sz = full ? 16 : 0;
    asm volatile("cp.async.cg.shared.global [%0], [%1], 16, %2;\n"
                 :: "r"(dst), "l"(src), "r"(sz));
}

__device__ __forceinline__ void mma_bf16(float c[4],
                                         const unsigned a[4],
                                         unsigned b0, unsigned b1) {
    asm volatile(
        "mma.sync.aligned.m16n8k16.row.col.f32.bf16.bf16.f32 "
        "{%0,%1,%2,%3}, {%4,%5,%6,%7}, {%8,%9}, {%0,%1,%2,%3};\n"
        : "+f"(c[0]), "+f"(c[1]), "+f"(c[2]), "+f"(c[3])
        : "r"(a[0]), "r"(a[1]), "r"(a[2]), "r"(a[3]), "r"(b0), "r"(b1));
}

__device__ __forceinline__ void ldsm_x4(unsigned r[4], uint32_t addr) {
    asm volatile("ldmatrix.sync.aligned.m8n8.x4.shared.b16 {%0,%1,%2,%3}, [%4];"
                 : "=r"(r[0]), "=r"(r[1]), "=r"(r[2]), "=r"(r[3]) : "r"(addr));
}
__device__ __forceinline__ void ldsm_x2(unsigned r[2], uint32_t addr) {
    asm volatile("ldmatrix.sync.aligned.m8n8.x2.shared.b16 {%0,%1}, [%2];"
                 : "=r"(r[0]), "=r"(r[1]) : "r"(addr));
}

extern __shared__ char dsm[];

__global__ __launch_bounds__(NTHR, 2) void gemm_kernel(const float* __restrict__ query,
                                                       const float* __restrict__ gamma,
                                                       const float* __restrict__ beta,
                                                       float* __restrict__ out_logits,
                                                       float* __restrict__ out_pred,
                                                       int write_pred) {
    const int b    = blockIdx.z;
    const int tm   = blockIdx.y;
    const int tid  = threadIdx.x;
    const int warp = tid >> 5, lane = tid & 31;
    const int wm = warp >> 2, wn = warp & 3;   // 2 m-warps x 4 n-warps
    const int qr = lane >> 2;          // 0..7
    const int qp = (lane & 3) * 2;     // 0,2,4,6

    const float* gq = query + ((size_t)b * QQ + (size_t)tm * BM) * H;
    const __nv_bfloat16* gBh = g_sh + (size_t)b * NK * H;
    const __nv_bfloat16* gBl = g_sl + (size_t)b * NK * H;

    const uint32_t smem_u32 = (uint32_t)__cvta_generic_to_shared(dsm);

    // ---- prologue: gamma/beta -> smem; per-row LN stats -> smem ----
    {
        reinterpret_cast<float4*>(dsm + OFF_GM)[tid] =
            reinterpret_cast<const float4*>(gamma)[tid];
        reinterpret_cast<float4*>(dsm + OFF_BT)[tid] =
            reinterpret_cast<const float4*>(beta)[tid];

        float* smean = (float*)(dsm + OFF_ST);
        float* srstd = (float*)(dsm + OFF_ST + 512);
        #pragma unroll 1
        for (int rr = 0; rr < 8; rr++) {
            const int row = warp * 8 + rr;
            const float4* xr = reinterpret_cast<const float4*>(gq + (size_t)row * H);
            float s = 0.0f, ss = 0.0f;
            #pragma unroll
            for (int j = 0; j < 8; j++) {
                float4 a = xr[j * 32 + lane];
                s  += (a.x + a.y) + (a.z + a.w);
                ss += fmaf(a.x, a.x, fmaf(a.y, a.y, fmaf(a.z, a.z, a.w * a.w)));
            }
            #pragma unroll
            for (int o = 16; o; o >>= 1) {
                s  += __shfl_xor_sync(0xffffffffu, s, o);
                ss += __shfl_xor_sync(0xffffffffu, ss, o);
            }
            if (lane == 0) {
                float mean = s * (1.0f / H);
                float var  = ss * (1.0f / H) - mean * mean;
                smean[row] = mean;
                srstd[row] = rsqrtf(var + 1e-5f);
            }
        }
    }
    __syncthreads();

    // per-thread A assignment: row = tid>>2 (0..63), k-eighth = (tid&3)*8
    const int arow = tid >> 2;
    const int ak0  = (tid & 3) * 8;
    const float amean = ((const float*)(dsm + OFF_ST))[arow];
    const float arstd = ((const float*)(dsm + OFF_ST + 512))[arow];
    const float* arow_p = gq + (size_t)arow * H;

    // ldmatrix lane->tile-row/col mappings
    const int a_lrow0 = wm * 32 + (lane & 7) + ((lane >> 3) & 1) * 8;
    const int a_lcol  = ((lane >> 4) & 1) * 8;
    const int b_lrow0 = wn * 56 + (lane & 7) + ((lane >> 4) & 1) * 8;
    const int b_lcol  = ((lane >> 3) & 1) * 8;
    const int t_lrow  = wn * 56 + 48 + (lane & 7);
    const int t_lcol  = ((lane >> 3) & 1) * 8;

    float acc[2][7][4];
    #pragma unroll
    for (int mf = 0; mf < 2; mf++)
        #pragma unroll
        for (int nf = 0; nf < 7; nf++)
            #pragma unroll
            for (int i = 0; i < 4; i++) acc[mf][nf][i] = 0.0f;

    // ---- B stage loader (cp.async; rows >= NK zero-filled) ----
    auto issueB = [&](int s, int buf) {
        const int kt = s * BKG;
        uint32_t base = smem_u32 + OFF_BRING + buf * BSTG_B;
        #pragma unroll
        for (int it = 0; it < 4; it++) {
            int idx = tid + it * NTHR;           // need < 896 (224 rows x 4)
            if (idx < 896) {
                int r = idx >> 2, k0 = (idx & 3) * 8;
                uint32_t off = (uint32_t)(r * BKP + k0) * 2;
                bool v = (r < NK);
                int rs = v ? r : 0;
                cp16(base + off,        gBh + (size_t)rs * H + kt + k0, v);
                cp16(base + BH_B + off, gBl + (size_t)rs * H + kt + k0, v);
            }
        }
        asm volatile("cp.async.commit_group;\n" ::);
    };

    // ---- A fetch (LDG fp32) + convert (LN affine -> split bf16 -> STS) ----
    float4 av[2];
    auto fetchA = [&](int s) {
        const float4* src = reinterpret_cast<const float4*>(arow_p + s * BKG + ak0);
        av[0] = src[0];
        av[1] = src[1];
    };
    auto convertA = [&](int s) {
        char* ab = dsm + (s & 1) * ABUF_B;
        uint2* dh = reinterpret_cast<uint2*>(ab + (arow * BKP + ak0) * 2);
        uint2* dl = reinterpret_cast<uint2*>(ab + AH_B + (arow * BKP + ak0) * 2);
        const float4* gg = reinterpret_cast<const float4*>(dsm + OFF_GM) + ((s * BKG + ak0) >> 2);
        const float4* bt = reinterpret_cast<const float4*>(dsm + OFF_BT) + ((s * BKG + ak0) >> 2);
        #pragma unroll
        for (int j = 0; j < 2; j++) {
            float4 x = av[j];
            float4 g = gg[j];
            float4 bb = bt[j];
            float o0 = (x.x - amean) * arstd * g.x + bb.x;
            float o1 = (x.y - amean) * arstd * g.y + bb.y;
            float o2 = (x.z - amean) * arstd * g.z + bb.z;
            float o3 = (x.w - amean) * arstd * g.w + bb.w;
            __nv_bfloat162 h01 = __floats2bfloat162_rn(o0, o1);
            __nv_bfloat162 h23 = __floats2bfloat162_rn(o2, o3);
            uint2 hp;
            hp.x = *reinterpret_cast<unsigned*>(&h01);
            hp.y = *reinterpret_cast<unsigned*>(&h23);
            dh[j] = hp;
            __nv_bfloat162 l01 = __floats2bfloat162_rn(o0 - __bfloat162float(h01.x),
                                                       o1 - __bfloat162float(h01.y));
            __nv_bfloat162 l23 = __floats2bfloat162_rn(o2 - __bfloat162float(h23.x),
                                                       o3 - __bfloat162float(h23.y));
            uint2 lp;
            lp.x = *reinterpret_cast<unsigned*>(&l01);
            lp.y = *reinterpret_cast<unsigned*>(&l23);
            dl[j] = lp;
        }
    };

    fetchA(0);
    issueB(0, 0);
    issueB(1, 1);
    convertA(0);
    fetchA(1);

    const int NIT = H / BKG;   // 32
    for (int i = 0; i < NIT; i++) {
        if (i < NIT - 1) asm volatile("cp.async.wait_group 1;\n" ::);
        else             asm volatile("cp.async.wait_group 0;\n" ::);
        __syncthreads();                      // A buf (i&1) + B stage i visible

        const uint32_t abase = smem_u32 + (i & 1) * ABUF_B;
        const uint32_t bbase = smem_u32 + OFF_BRING + (i & 1) * BSTG_B;

        #pragma unroll
        for (int ks = 0; ks < BKG; ks += 16) {
            unsigned ah[2][4], al[2][4];
            #pragma unroll
            for (int mf = 0; mf < 2; mf++) {
                uint32_t aaddr = abase +
                    (uint32_t)((a_lrow0 + mf * 16) * BKP + ks + a_lcol) * 2;
                ldsm_x4(ah[mf], aaddr);
                ldsm_x4(al[mf], aaddr + AH_B);
            }
            #pragma unroll
            for (int p = 0; p < 3; p++) {
                unsigned bh[4], bl[4];
                uint32_t baddr = bbase +
                    (uint32_t)((b_lrow0 + p * 16) * BKP + ks + b_lcol) * 2;
                ldsm_x4(bh, baddr);
                ldsm_x4(bl, baddr + BH_B);
                // pass 1: ah . bh
                mma_bf16(acc[0][2 * p],     ah[0], bh[0], bh[1]);
                mma_bf16(acc[1][2 * p],     ah[1], bh[0], bh[1]);
                mma_bf16(acc[0][2 * p + 1], ah[0], bh[2], bh[3]);
                mma_bf16(acc[1][2 * p + 1], ah[1], bh[2], bh[3]);
                // pass 2: ah . bl
                mma_bf16(acc[0][2 * p],     ah[0], bl[0], bl[1]);
                mma_bf16(acc[1][2 * p],     ah[1], bl[0], bl[1]);
                mma_bf16(acc[0][2 * p + 1], ah[0], bl[2], bl[3]);
                mma_bf16(acc[1][2 * p + 1], ah[1], bl[2], bl[3]);
                // pass 3: al . bh
                mma_bf16(acc[0][2 * p],     al[0], bh[0], bh[1]);
                mma_bf16(acc[1][2 * p],     al[1], bh[0], bh[1]);
                mma_bf16(acc[0][2 * p + 1], al[0], bh[2], bh[3]);
                mma_bf16(acc[1][2 * p + 1], al[1], bh[2], bh[3]);
            }
            {   // tail nf = 6 (n 48..55 of this warp's slice)
                unsigned th[2], tl[2];
                uint32_t taddr = bbase +
                    (uint32_t)(t_lrow * BKP + ks + t_lcol) * 2;
                ldsm_x2(th, taddr);
                ldsm_x2(tl, taddr + BH_B);
                mma_bf16(acc[0][6], ah[0], th[0], th[1]);
                mma_bf16(acc[1][6], ah[1], th[0], th[1]);
                mma_bf16(acc[0][6], ah[0], tl[0], tl[1]);
                mma_bf16(acc[1][6], ah[1], tl[0], tl[1]);
                mma_bf16(acc[0][6], al[0], th[0], th[1]);
                mma_bf16(acc[1][6], al[1], th[0], th[1]);
            }
        }

        // prepare next A stage (buf (i+1)&1, last read in iter i-1: safe)
        if (i + 1 < NIT) {
            convertA(i + 1);
            if (i + 2 < NIT) fetchA(i + 2);
        }

        // all warps done reading B buf (i&1) -> safe to refill it with stage i+2
        __syncthreads();
        if (i + 2 < NIT) issueB(i + 2, i & 1);
    }

    // ---- fused epilogue: all 64 rows staged at once ----
    float* zs = (float*)dsm;                    // 64 x ZST floats = 53.8 KB
    #pragma unroll
    for (int mf = 0; mf < 2; mf++)
        #pragma unroll
        for (int nf = 0; nf < 7; nf++) {
            int colbase = wn * 56 + nf * 8;
            if (colbase < BNV) {                // skip pad fragments
                int r0  = wm * 32 + mf * 16 + qr;
                int col = colbase + qp;
                *reinterpret_cast<float2*>(&zs[r0 * ZST + col]) =
                    make_float2(acc[mf][nf][0], acc[mf][nf][1]);
                *reinterpret_cast<float2*>(&zs[(r0 + 8) * ZST + col]) =
                    make_float2(acc[mf][nf][2], acc[mf][nf][3]);
            }
        }
    __syncthreads();

    const float NEGF = -3.402823466e38f;
    const float POSF =  3.402823466e38f;
    #pragma unroll 1
    for (int rr = 0; rr < 8; rr++) {
        int rl = warp * 8 + rr;
        int gq_ = tm * BM + rl;
        size_t orow = ((size_t)b * QQ + gq_) * (NN + 1);

        float m = NEGF;
        if (lane < NN) {
            #pragma unroll
            for (int j = 0; j < KKK; j++)
                m = fmaxf(m, zs[rl * ZST + lane * KKK + j]);
            out_logits[orow + lane] = m;
        }

        float mv = (lane < NN) ? m : POSF;
        #pragma unroll
        for (int o = 16; o; o >>= 1)
            mv = fminf(mv, __shfl_xor_sync(0xffffffffu, mv, o));
        if (lane == 0) out_logits[orow + NN] = mv - 1.0f;

        float v  = (lane < NN) ? m : NEGF;
        int  idx = lane;
        #pragma unroll
        for (int o = 16; o; o >>= 1) {
            float ov = __shfl_xor_sync(0xffffffffu, v, o);
            int   oi = __shfl_xor_sync(0xffffffffu, idx, o);
            if (ov > v || (ov == v && oi < idx)) { v = ov; idx = oi; }
        }
        if (lane == 0 && write_pred)
            out_pred[(size_t)b * QQ + gq_] = (float)idx;
    }
}

// ---------------------------------------------------------------------------
extern "C" void kernel_launch(void* const* d_in, const int* in_sizes, int n_in,
                              void* d_out, int out_size) {
    const float* support = (const float*)d_in[0];
    const float* query   = (const float*)d_in[1];
    const float* gamma   = (const float*)d_in[2];
    const float* beta    = (const float*)d_in[3];
    float* out = (float*)d_out;

    cudaFuncSetAttribute(gemm_kernel,
                         cudaFuncAttributeMaxDynamicSharedMemorySize, SMEM_TOTAL);

    ln_kernel<<<SROWS / 8, 256>>>(support, gamma, beta);

    const int logits_elems = BATCH * QQ * (NN + 1);  // 1,376,256
    const int write_pred   = (out_size >= logits_elems + QROWS) ? 1 : 0;

    dim3 grid(1, QQ / BM, BATCH);   // (1, 32, 32) = 1024 CTAs
    gemm_kernel<<<grid, NTHR, SMEM_TOTAL>>>(query, gamma, beta,
                                            out, out + logits_elems, write_pred);
}

// round 14
// speedup vs baseline: 1.1196x; 1.0264x over previous
#include <cuda_runtime.h>
#include <cuda_bf16.h>
#include <cstdint>

// Problem constants (fixed-shape benchmark)
#define H      1024
#define BATCH  32
#define NN     20        // N
#define KKK    10        // K (group size)
#define NK     200       // N*K
#define QQ     2048      // Q_total
#define SROWS  (BATCH * NK)   // 6400 support rows
#define QROWS  (BATCH * QQ)   // 65536 query rows

// Scratch (allocation-free: __device__ globals) — support LN only
__device__ __nv_bfloat16 g_sh[(size_t)SROWS * H];   // support LN hi
__device__ __nv_bfloat16 g_sl[(size_t)SROWS * H];   // support LN lo

// ---------------------------------------------------------------------------
// LayerNorm for SUPPORT rows, warp-per-row: 8 warps/block = 8 rows/block.
// ---------------------------------------------------------------------------
__global__ __launch_bounds__(256) void ln_kernel(const float* __restrict__ x,
                          const float* __restrict__ gamma,
                          const float* __restrict__ beta) {
    const int lane = threadIdx.x & 31;
    const int warp = threadIdx.x >> 5;
    const int row  = blockIdx.x * 8 + warp;

    const float4* xr = reinterpret_cast<const float4*>(x) + (size_t)row * (H / 4);
    float4 a[8];
    #pragma unroll
    for (int i = 0; i < 8; i++) a[i] = xr[lane + i * 32];

    float s = 0.0f, ss = 0.0f;
    #pragma unroll
    for (int i = 0; i < 8; i++) {
        s  += (a[i].x + a[i].y) + (a[i].z + a[i].w);
        ss += fmaf(a[i].x, a[i].x, fmaf(a[i].y, a[i].y,
               fmaf(a[i].z, a[i].z, a[i].w * a[i].w)));
    }
    #pragma unroll
    for (int o = 16; o; o >>= 1) {
        s  += __shfl_xor_sync(0xffffffffu, s, o);
        ss += __shfl_xor_sync(0xffffffffu, ss, o);
    }
    const float mean = s * (1.0f / H);
    const float var  = ss * (1.0f / H) - mean * mean;
    const float rstd = rsqrtf(var + 1e-5f);

    uint2* dsth = reinterpret_cast<uint2*>(g_sh + (size_t)row * H);
    uint2* dstl = reinterpret_cast<uint2*>(g_sl + (size_t)row * H);
    const float4* g4 = reinterpret_cast<const float4*>(gamma);
    const float4* b4 = reinterpret_cast<const float4*>(beta);

    #pragma unroll
    for (int i = 0; i < 8; i++) {
        const int idx = lane + i * 32;
        float4 g  = g4[idx];
        float4 bb = b4[idx];
        float o0 = (a[i].x - mean) * rstd * g.x + bb.x;
        float o1 = (a[i].y - mean) * rstd * g.y + bb.y;
        float o2 = (a[i].z - mean) * rstd * g.z + bb.z;
        float o3 = (a[i].w - mean) * rstd * g.w + bb.w;

        __nv_bfloat162 h01 = __floats2bfloat162_rn(o0, o1);
        __nv_bfloat162 h23 = __floats2bfloat162_rn(o2, o3);
        uint2 hp;
        hp.x = *reinterpret_cast<unsigned*>(&h01);
        hp.y = *reinterpret_cast<unsigned*>(&h23);
        dsth[idx] = hp;

        __nv_bfloat162 l01 = __floats2bfloat162_rn(o0 - __bfloat162float(h01.x),
                                                   o1 - __bfloat162float(h01.y));
        __nv_bfloat162 l23 = __floats2bfloat162_rn(o2 - __bfloat162float(h23.x),
                                                   o3 - __bfloat162float(h23.y));
        uint2 lp;
        lp.x = *reinterpret_cast<unsigned*>(&l01);
        lp.y = *reinterpret_cast<unsigned*>(&l23);
        dstl[idx] = lp;
    }
}

// ---------------------------------------------------------------------------
// Fused kernel: query LN (stats prologue + on-the-fly split-bf16 convert)
// + tensor-core batched GEMM (split-bf16 x3) + max/min/argmax epilogue.
// CTA tile: BM=64 x BN=224 (valid outputs n<200), BK=32.
// 256 threads / 8 warps in a 2x4 grid; warp tile 32x56.
// TWO CTAs per SM. Pad-skip: warp wn=3 computes only its valid n<200
// fragments; B rows >= 200 never loaded (smem bytes are the binding pipe).
// ---------------------------------------------------------------------------
#define BM   64
#define BN   224         // padded; valid output n < NK (200)
#define BNV  208
#define BKG  32
#define BKP  40          // padded smem k-stride (bf16); conflict-free LDSM
#define NTHR 256

#define AH_B      (BM * BKP * 2)            // 5120
#define ABUF_B    (2 * AH_B)                // 10240 (Ah + Al)
#define OFF_BRING (2 * ABUF_B)              // 20480
#define BH_B      (BN * BKP * 2)            // 17920
#define BSTG_B    (2 * BH_B)                // 35840 (Bh + Bl)
#define NBSTG     2
#define OFF_GM    (OFF_BRING + NBSTG * BSTG_B)  // 92160
#define OFF_BT    (OFF_GM + 4096)           // 96256
#define OFF_ST    (OFF_BT + 4096)           // 100352 (mean[64], rstd[64])
#define SMEM_TOTAL (OFF_ST + 1024)          // 101376 (x2 CTAs = 198KB < 228KB)
#define ZST       210                       // epilogue smem row stride (floats)

__device__ __forceinline__ void cp16(uint32_t dst, const void* src, bool full) {
    int sz = full ? 16 : 0;
    asm volatile("cp.async.cg.shared.global [%0], [%1], 16, %2;\n"
                 :: "r"(dst), "l"(src), "r"(sz));
}

__device__ __forceinline__ void mma_bf16(float c[4],
                                         const unsigned a[4],
                                         unsigned b0, unsigned b1) {
    asm volatile(
        "mma.sync.aligned.m16n8k16.row.col.f32.bf16.bf16.f32 "
        "{%0,%1,%2,%3}, {%4,%5,%6,%7}, {%8,%9}, {%0,%1,%2,%3};\n"
        : "+f"(c[0]), "+f"(c[1]), "+f"(c[2]), "+f"(c[3])
        : "r"(a[0]), "r"(a[1]), "r"(a[2]), "r"(a[3]), "r"(b0), "r"(b1));
}

__device__ __forceinline__ void ldsm_x4(unsigned r[4], uint32_t addr) {
    asm volatile("ldmatrix.sync.aligned.m8n8.x4.shared.b16 {%0,%1,%2,%3}, [%4];"
                 : "=r"(r[0]), "=r"(r[1]), "=r"(r[2]), "=r"(r[3]) : "r"(addr));
}
__device__ __forceinline__ void ldsm_x2(unsigned r[2], uint32_t addr) {
    asm volatile("ldmatrix.sync.aligned.m8n8.x2.shared.b16 {%0,%1}, [%2];"
                 : "=r"(r[0]), "=r"(r[1]) : "r"(addr));
}

extern __shared__ char dsm[];

__global__ __launch_bounds__(NTHR, 2) void gemm_kernel(const float* __restrict__ query,
                                                       const float* __restrict__ gamma,
                                                       const float* __restrict__ beta,
                                                       float* __restrict__ out_logits,
                                                       float* __restrict__ out_pred,
                                                       int write_pred) {
    const int b    = blockIdx.z;
    const int tm   = blockIdx.y;
    const int tid  = threadIdx.x;
    const int warp = tid >> 5, lane = tid & 31;
    const int wm = warp >> 2, wn = warp & 3;   // 2 m-warps x 4 n-warps
    const int qr = lane >> 2;          // 0..7
    const int qp = (lane & 3) * 2;     // 0,2,4,6

    const float* gq = query + ((size_t)b * QQ + (size_t)tm * BM) * H;
    const __nv_bfloat16* gBh = g_sh + (size_t)b * NK * H;
    const __nv_bfloat16* gBl = g_sl + (size_t)b * NK * H;

    const uint32_t smem_u32 = (uint32_t)__cvta_generic_to_shared(dsm);

    // ---- prologue: gamma/beta -> smem; per-row LN stats -> smem ----
    {
        reinterpret_cast<float4*>(dsm + OFF_GM)[tid] =
            reinterpret_cast<const float4*>(gamma)[tid];
        reinterpret_cast<float4*>(dsm + OFF_BT)[tid] =
            reinterpret_cast<const float4*>(beta)[tid];

        float* smean = (float*)(dsm + OFF_ST);
        float* srstd = (float*)(dsm + OFF_ST + 512);
        #pragma unroll 1
        for (int rr = 0; rr < 8; rr++) {
            const int row = warp * 8 + rr;
            const float4* xr = reinterpret_cast<const float4*>(gq + (size_t)row * H);
            float s = 0.0f, ss = 0.0f;
            #pragma unroll
            for (int j = 0; j < 8; j++) {
                float4 a = xr[j * 32 + lane];
                s  += (a.x + a.y) + (a.z + a.w);
                ss += fmaf(a.x, a.x, fmaf(a.y, a.y, fmaf(a.z, a.z, a.w * a.w)));
            }
            #pragma unroll
            for (int o = 16; o; o >>= 1) {
                s  += __shfl_xor_sync(0xffffffffu, s, o);
                ss += __shfl_xor_sync(0xffffffffu, ss, o);
            }
            if (lane == 0) {
                float mean = s * (1.0f / H);
                float var  = ss * (1.0f / H) - mean * mean;
                smean[row] = mean;
                srstd[row] = rsqrtf(var + 1e-5f);
            }
        }
    }
    __syncthreads();

    // per-thread A assignment: row = tid>>2 (0..63), k-eighth = (tid&3)*8
    const int arow = tid >> 2;
    const int ak0  = (tid & 3) * 8;
    const float amean = ((const float*)(dsm + OFF_ST))[arow];
    const float arstd = ((const float*)(dsm + OFF_ST + 512))[arow];
    const float* arow_p = gq + (size_t)arow * H;

    // ldmatrix lane->tile-row/col mappings
    const int a_lrow0 = wm * 32 + (lane & 7) + ((lane >> 3) & 1) * 8;
    const int a_lcol  = ((lane >> 4) & 1) * 8;
    const int b_lrow0 = wn * 56 + (lane & 7) + ((lane >> 4) & 1) * 8;
    const int b_lcol  = ((lane >> 3) & 1) * 8;
    const int t_lrow  = wn * 56 + 48 + (lane & 7);
    const int t_lcol  = ((lane >> 3) & 1) * 8;

    float acc[2][7][4];
    #pragma unroll
    for (int mf = 0; mf < 2; mf++)
        #pragma unroll
        for (int nf = 0; nf < 7; nf++)
            #pragma unroll
            for (int i = 0; i < 4; i++) acc[mf][nf][i] = 0.0f;

    // ---- B stage loader (cp.async; rows >= NK never loaded, never read) ----
    auto issueB = [&](int s, int buf) {
        const int kt = s * BKG;
        uint32_t base = smem_u32 + OFF_BRING + buf * BSTG_B;
        #pragma unroll
        for (int it = 0; it < 4; it++) {
            int idx = tid + it * NTHR;           // valid rows: r < 200
            int r = idx >> 2, k0 = (idx & 3) * 8;
            if (r < NK) {
                uint32_t off = (uint32_t)(r * BKP + k0) * 2;
                cp16(base + off,        gBh + (size_t)r * H + kt + k0, true);
                cp16(base + BH_B + off, gBl + (size_t)r * H + kt + k0, true);
            }
        }
        asm volatile("cp.async.commit_group;\n" ::);
    };

    // ---- A fetch (LDG fp32) + convert (LN affine -> split bf16 -> STS) ----
    float4 av[2];
    auto fetchA = [&](int s) {
        const float4* src = reinterpret_cast<const float4*>(arow_p + s * BKG + ak0);
        av[0] = src[0];
        av[1] = src[1];
    };
    auto convertA = [&](int s) {
        char* ab = dsm + (s & 1) * ABUF_B;
        uint2* dh = reinterpret_cast<uint2*>(ab + (arow * BKP + ak0) * 2);
        uint2* dl = reinterpret_cast<uint2*>(ab + AH_B + (arow * BKP + ak0) * 2);
        const float4* gg = reinterpret_cast<const float4*>(dsm + OFF_GM) + ((s * BKG + ak0) >> 2);
        const float4* bt = reinterpret_cast<const float4*>(dsm + OFF_BT) + ((s * BKG + ak0) >> 2);
        #pragma unroll
        for (int j = 0; j < 2; j++) {
            float4 x = av[j];
            float4 g = gg[j];
            float4 bb = bt[j];
            float o0 = (x.x - amean) * arstd * g.x + bb.x;
            float o1 = (x.y - amean) * arstd * g.y + bb.y;
            float o2 = (x.z - amean) * arstd * g.z + bb.z;
            float o3 = (x.w - amean) * arstd * g.w + bb.w;
            __nv_bfloat162 h01 = __floats2bfloat162_rn(o0, o1);
            __nv_bfloat162 h23 = __floats2bfloat162_rn(o2, o3);
            uint2 hp;
            hp.x = *reinterpret_cast<unsigned*>(&h01);
            hp.y = *reinterpret_cast<unsigned*>(&h23);
            dh[j] = hp;
            __nv_bfloat162 l01 = __floats2bfloat162_rn(o0 - __bfloat162float(h01.x),
                                                       o1 - __bfloat162float(h01.y));
            __nv_bfloat162 l23 = __floats2bfloat162_rn(o2 - __bfloat162float(h23.x),
                                                       o3 - __bfloat162float(h23.y));
            uint2 lp;
            lp.x = *reinterpret_cast<unsigned*>(&l01);
            lp.y = *reinterpret_cast<unsigned*>(&l23);
            dl[j] = lp;
        }
    };

    fetchA(0);
    issueB(0, 0);
    issueB(1, 1);
    convertA(0);
    fetchA(1);

    const int NIT = H / BKG;   // 32
    for (int i = 0; i < NIT; i++) {
        if (i < NIT - 1) asm volatile("cp.async.wait_group 1;\n" ::);
        else             asm volatile("cp.async.wait_group 0;\n" ::);
        __syncthreads();                      // A buf (i&1) + B stage i visible

        const uint32_t abase = smem_u32 + (i & 1) * ABUF_B;
        const uint32_t bbase = smem_u32 + OFF_BRING + (i & 1) * BSTG_B;

        #pragma unroll
        for (int ks = 0; ks < BKG; ks += 16) {
            unsigned ah[2][4], al[2][4];
            #pragma unroll
            for (int mf = 0; mf < 2; mf++) {
                uint32_t aaddr = abase +
                    (uint32_t)((a_lrow0 + mf * 16) * BKP + ks + a_lcol) * 2;
                ldsm_x4(ah[mf], aaddr);
                ldsm_x4(al[mf], aaddr + AH_B);
            }
            #pragma unroll
            for (int p = 0; p < 3; p++) {
                if (p == 2 && wn == 3) continue;   // n 200-215: pad, skip
                unsigned bh[4], bl[4];
                uint32_t baddr = bbase +
                    (uint32_t)((b_lrow0 + p * 16) * BKP + ks + b_lcol) * 2;
                ldsm_x4(bh, baddr);
                ldsm_x4(bl, baddr + BH_B);
                // pass 1: ah . bh
                mma_bf16(acc[0][2 * p],     ah[0], bh[0], bh[1]);
                mma_bf16(acc[1][2 * p],     ah[1], bh[0], bh[1]);
                mma_bf16(acc[0][2 * p + 1], ah[0], bh[2], bh[3]);
                mma_bf16(acc[1][2 * p + 1], ah[1], bh[2], bh[3]);
                // pass 2: ah . bl
                mma_bf16(acc[0][2 * p],     ah[0], bl[0], bl[1]);
                mma_bf16(acc[1][2 * p],     ah[1], bl[0], bl[1]);
                mma_bf16(acc[0][2 * p + 1], ah[0], bl[2], bl[3]);
                mma_bf16(acc[1][2 * p + 1], ah[1], bl[2], bl[3]);
                // pass 3: al . bh
                mma_bf16(acc[0][2 * p],     al[0], bh[0], bh[1]);
                mma_bf16(acc[1][2 * p],     al[1], bh[0], bh[1]);
                mma_bf16(acc[0][2 * p + 1], al[0], bh[2], bh[3]);
                mma_bf16(acc[1][2 * p + 1], al[1], bh[2], bh[3]);
            }
            if (wn != 3) {   // tail nf = 6 (n 48..55 of this warp's slice)
                unsigned th[2], tl[2];
                uint32_t taddr = bbase +
                    (uint32_t)(t_lrow * BKP + ks + t_lcol) * 2;
                ldsm_x2(th, taddr);
                ldsm_x2(tl, taddr + BH_B);
                mma_bf16(acc[0][6], ah[0], th[0], th[1]);
                mma_bf16(acc[1][6], ah[1], th[0], th[1]);
                mma_bf16(acc[0][6], ah[0], tl[0], tl[1]);
                mma_bf16(acc[1][6], ah[1], tl[0], tl[1]);
                mma_bf16(acc[0][6], al[0], th[0], th[1]);
                mma_bf16(acc[1][6], al[1], th[0], th[1]);
            }
        }

        // prepare next A stage (buf (i+1)&1, last read in iter i-1: safe)
        if (i + 1 < NIT) {
            convertA(i + 1);
            if (i + 2 < NIT) fetchA(i + 2);
        }

        // all warps done reading B buf (i&1) -> safe to refill with stage i+2
        __syncthreads();
        if (i + 2 < NIT) issueB(i + 2, i & 1);
    }

    // ---- fused epilogue: all 64 rows staged at once ----
    float* zs = (float*)dsm;                    // 64 x ZST floats = 53.8 KB
    #pragma unroll
    for (int mf = 0; mf < 2; mf++)
        #pragma unroll
        for (int nf = 0; nf < 7; nf++) {
            int colbase = wn * 56 + nf * 8;
            if (colbase < NK) {                 // write valid columns only
                int r0  = wm * 32 + mf * 16 + qr;
                int col = colbase + qp;
                *reinterpret_cast<float2*>(&zs[r0 * ZST + col]) =
                    make_float2(acc[mf][nf][0], acc[mf][nf][1]);
                *reinterpret_cast<float2*>(&zs[(r0 + 8) * ZST + col]) =
                    make_float2(acc[mf][nf][2], acc[mf][nf][3]);
            }
        }
    __syncthreads();

    const float NEGF = -3.402823466e38f;
    const float POSF =  3.402823466e38f;
    #pragma unroll 1
    for (int rr = 0; rr < 8; rr++) {
        int rl = warp * 8 + rr;
        int gq_ = tm * BM + rl;
        size_t orow = ((size_t)b * QQ + gq_) * (NN + 1);

        float m = NEGF;
        if (lane < NN) {
            #pragma unroll
            for (int j = 0; j < KKK; j++)
                m = fmaxf(m, zs[rl * ZST + lane * KKK + j]);
            out_logits[orow + lane] = m;
        }

        float mv = (lane < NN) ? m : POSF;
        #pragma unroll
        for (int o = 16; o; o >>= 1)
            mv = fminf(mv, __shfl_xor_sync(0xffffffffu, mv, o));
        if (lane == 0) out_logits[orow + NN] = mv - 1.0f;

        float v  = (lane < NN) ? m : NEGF;
        int  idx = lane;
        #pragma unroll
        for (int o = 16; o; o >>= 1) {
            float ov = __shfl_xor_sync(0xffffffffu, v, o);
            int   oi = __shfl_xor_sync(0xffffffffu, idx, o);
            if (ov > v || (ov == v && oi < idx)) { v = ov; idx = oi; }
        }
        if (lane == 0 && write_pred)
            out_pred[(size_t)b * QQ + gq_] = (float)idx;
    }
}

// ---------------------------------------------------------------------------
extern "C" void kernel_launch(void* const* d_in, const int* in_sizes, int n_in,
                              void* d_out, int out_size) {
    const float* support = (const float*)d_in[0];
    const float* query   = (const float*)d_in[1];
    const float* gamma   = (const float*)d_in[2];
    const float* beta    = (const float*)d_in[3];
    float* out = (float*)d_out;

    cudaFuncSetAttribute(gemm_kernel,
                         cudaFuncAttributeMaxDynamicSharedMemorySize, SMEM_TOTAL);

    ln_kernel<<<SROWS / 8, 256>>>(support, gamma, beta);

    const int logits_elems = BATCH * QQ * (NN + 1);  // 1,376,256
    const int write_pred   = (out_size >= logits_elems + QROWS) ? 1 : 0;

    dim3 grid(1, QQ / BM, BATCH);   // (1, 32, 32) = 1024 CTAs
    gemm_kernel<<<grid, NTHR, SMEM_TOTAL>>>(query, gamma, beta,
                                            out, out + logits_elems, write_pred);
}